// round 1
// baseline (speedup 1.0000x reference)
#include <cuda_runtime.h>
#include <cstdint>

// Problem constants (fixed by setup_inputs)
#define BATCH 16
#define NPTS  256
#define NHEAD 8
#define HID   64
#define NIN   12

#define PIX_PER_THREAD 4
#define TPB 128

// ---------------- packed f32x2 helpers ----------------
__device__ __forceinline__ unsigned long long pack2(float lo, float hi) {
    unsigned long long r;
    asm("mov.b64 %0, {%1, %2};" : "=l"(r) : "f"(lo), "f"(hi));
    return r;
}
__device__ __forceinline__ void unpack2(unsigned long long v, float& lo, float& hi) {
    asm("mov.b64 {%0, %1}, %2;" : "=f"(lo), "=f"(hi) : "l"(v));
}
__device__ __forceinline__ unsigned long long ffma2(unsigned long long a,
                                                    unsigned long long b,
                                                    unsigned long long c) {
    unsigned long long d;
    asm("fma.rn.f32x2 %0, %1, %2, %3;" : "=l"(d) : "l"(a), "l"(b), "l"(c));
    return d;
}

__device__ __forceinline__ float silu_f(float x) {
    // x * sigmoid(x) = x / (1 + exp(-x))
    return __fdividef(x, 1.0f + __expf(-x));
}

__device__ __forceinline__ void compute_features(float4 f, float* o) {
    float rx = f.x, ry = f.y, rvx = f.z, rvy = f.w;
    float d2    = fmaf(rx, rx, ry * ry);
    float dist  = __fsqrt_rn(d2 + 1e-6f);
    float invde = __fdividef(1.0f, dist + 1e-6f);
    float invd  = __fdividef(1.0f, dist + 0.1f);
    float ssq   = fmaf(rvx, rvx, rvy * rvy);
    float rsp   = __fsqrt_rn(ssq + 1e-6f);
    float dot   = fmaf(rvx, rx, rvy * ry);
    float closing = dot * invde;
    // tanh(a) with a = -dot/(ssq+1e-6):  tanh(a) = 1 - 2/(exp(2a)+1)
    float a    = -__fdividef(dot, ssq + 1e-6f);
    float e2a  = __expf(2.0f * a);            // inf -> ttca=1, 0 -> ttca=-1 (correct limits)
    float ttca = 1.0f - __fdividef(2.0f, e2a + 1.0f);
    o[0]  = rx;       o[1]  = ry;       o[2]  = rvx;      o[3]  = rvy;
    o[4]  = dist;     o[5]  = invd;     o[6]  = rsp;      o[7]  = closing;
    o[8]  = rx * invde; o[9] = ry * invde; o[10] = ttca;  o[11] = dot;
}

__global__ void __launch_bounds__(TPB)
relfeat_mlp_kernel(const float* __restrict__ ff,
                   const float* __restrict__ W1,
                   const float* __restrict__ b1,
                   const float* __restrict__ W2,
                   const float* __restrict__ b2,
                   float* __restrict__ out) {
    // Weights cached in shared, pre-duplicated into both f32x2 halves so a
    // single LDS.64 feeds two packed FFMA2s (4 scalar FMAs).
    __shared__ unsigned long long sW1[NIN * HID];   // [i][j], dup
    __shared__ unsigned long long sB1[HID];
    __shared__ unsigned long long sW2[HID * NHEAD]; // [j][o], dup
    __shared__ unsigned long long sB2[NHEAD];

    for (int i = threadIdx.x; i < NIN * HID; i += TPB) { float w = W1[i]; sW1[i] = pack2(w, w); }
    for (int i = threadIdx.x; i < HID;       i += TPB) { float w = b1[i]; sB1[i] = pack2(w, w); }
    for (int i = threadIdx.x; i < HID*NHEAD; i += TPB) { float w = W2[i]; sW2[i] = pack2(w, w); }
    for (int i = threadIdx.x; i < NHEAD;     i += TPB) { float w = b2[i]; sB2[i] = pack2(w, w); }
    __syncthreads();

    int t   = blockIdx.x * TPB + threadIdx.x;
    int pix = t * PIX_PER_THREAD;                  // linear pixel index (b*N+n)*N+m
    int m   = pix & (NPTS - 1);
    int n   = (pix >> 8) & (NPTS - 1);
    int b   = pix >> 16;

    // Load 4 consecutive pixels' raw features (64B contiguous per thread)
    const float4* ffp = reinterpret_cast<const float4*>(ff);
    float4 r0 = ffp[pix + 0];
    float4 r1 = ffp[pix + 1];
    float4 r2 = ffp[pix + 2];
    float4 r3 = ffp[pix + 3];

    float f0[NIN], f1[NIN], f2[NIN], f3[NIN];
    compute_features(r0, f0);
    compute_features(r1, f1);
    compute_features(r2, f2);
    compute_features(r3, f3);

    unsigned long long fA[NIN], fB[NIN];
    #pragma unroll
    for (int i = 0; i < NIN; i++) {
        fA[i] = pack2(f0[i], f1[i]);
        fB[i] = pack2(f2[i], f3[i]);
    }

    unsigned long long oA[NHEAD], oB[NHEAD];
    #pragma unroll
    for (int o = 0; o < NHEAD; o++) { oA[o] = sB2[o]; oB[o] = sB2[o]; }

    #pragma unroll 4
    for (int j = 0; j < HID; j++) {
        unsigned long long accA = sB1[j];
        unsigned long long accB = accA;
        #pragma unroll
        for (int i = 0; i < NIN; i++) {
            unsigned long long w = sW1[i * HID + j];
            accA = ffma2(fA[i], w, accA);
            accB = ffma2(fB[i], w, accB);
        }
        float x0, x1, x2, x3;
        unpack2(accA, x0, x1);
        unpack2(accB, x2, x3);
        x0 = silu_f(x0); x1 = silu_f(x1); x2 = silu_f(x2); x3 = silu_f(x3);
        unsigned long long hA = pack2(x0, x1);
        unsigned long long hB = pack2(x2, x3);
        #pragma unroll
        for (int o = 0; o < NHEAD; o++) {
            unsigned long long w = sW2[j * NHEAD + o];
            oA[o] = ffma2(hA, w, oA[o]);
            oB[o] = ffma2(hB, w, oB[o]);
        }
    }

    // Output layout (B, H, N, N); 4 consecutive m -> one float4 store per head
    float4* outv = reinterpret_cast<float4*>(out);
    int base = (((b * NHEAD) * NPTS) + n) * (NPTS / 4) + (m >> 2);
    #pragma unroll
    for (int o = 0; o < NHEAD; o++) {
        float v0, v1, v2, v3;
        unpack2(oA[o], v0, v1);
        unpack2(oB[o], v2, v3);
        outv[base + o * NPTS * (NPTS / 4)] = make_float4(v0, v1, v2, v3);
    }
}

extern "C" void kernel_launch(void* const* d_in, const int* in_sizes, int n_in,
                              void* d_out, int out_size) {
    const float* ff = (const float*)d_in[0];
    const float* W1 = (const float*)d_in[1];
    const float* b1 = (const float*)d_in[2];
    const float* W2 = (const float*)d_in[3];
    const float* b2 = (const float*)d_in[4];
    float* out = (float*)d_out;

    // total pixels = out_size / NHEAD; threads = pixels / 4
    int pixels  = out_size / NHEAD;                 // 1,048,576
    int threads = pixels / PIX_PER_THREAD;          // 262,144
    int blocks  = threads / TPB;                    // 2048
    relfeat_mlp_kernel<<<blocks, TPB>>>(ff, W1, b1, W2, b2, out);
}